// round 6
// baseline (speedup 1.0000x reference)
#include <cuda_runtime.h>
#include <cuda_fp16.h>
#include <cstdint>

#define Bb 8
#define Nn 2048
#define ALPHA 0.2f

// ---------------- device globals (no allocation allowed) -------------------
__device__ float  g_s[Bb * Nn];
__device__ float  g_t[Bb * Nn];
__device__ float  g_tmax[Bb];
__device__ __half g_WhT[Bb * 64 * Nn];   // [b][f][j], fp16, 2MB

// ---------------- PTX helpers ----------------------------------------------
__device__ __forceinline__ uint32_t su32(const void* p) {
    uint32_t a;
    asm("{ .reg .u64 t; cvta.to.shared.u64 t, %1; cvt.u32.u64 %0, t; }"
        : "=r"(a) : "l"(p));
    return a;
}
#define CVTH2(r, lo, hi) \
    asm("cvt.rn.f16x2.f32 %0, %2, %1;" : "=r"(r) : "f"(lo), "f"(hi))

#define LDSM4(r0, r1, r2, r3, addr) \
    asm volatile("ldmatrix.sync.aligned.m8n8.x4.shared.b16 {%0,%1,%2,%3}, [%4];" \
                 : "=r"(r0), "=r"(r1), "=r"(r2), "=r"(r3) : "r"(addr))

#define MMA16816(dd, a0, a1, a2, a3, b0, b1) \
    asm volatile("mma.sync.aligned.m16n8k16.row.col.f32.f16.f16.f32 " \
                 "{%0,%1,%2,%3}, {%4,%5,%6,%7}, {%8,%9}, {%0,%1,%2,%3};" \
                 : "+f"((dd)[0]), "+f"((dd)[1]), "+f"((dd)[2]), "+f"((dd)[3]) \
                 : "r"(a0), "r"(a1), "r"(a2), "r"(a3), "r"(b0), "r"(b1))

#define CP16(dst, src) \
    asm volatile("cp.async.cg.shared.global [%0], [%1], 16;" \
                 :: "r"(dst), "l"(src) : "memory")
#define CP_COMMIT() asm volatile("cp.async.commit_group;" ::: "memory")
#define CP_WAIT1()  asm volatile("cp.async.wait_group 1;" ::: "memory")

// ---------------------------------------------------------------------------
// Kernel A: Wh = h @ W (f32 regs); emits s, t (f32) and WhT (fp16, [b][f][j]).
// ---------------------------------------------------------------------------
__global__ void __launch_bounds__(256) kA(const float* __restrict__ h,
                                          const float* __restrict__ W,
                                          const float* __restrict__ a) {
    __shared__ float  Wsh[64 * 64];
    __shared__ float  hsh[16][64];
    __shared__ float  red[16][2][2];
    __shared__ __half Tsh[64][40];

    int t = threadIdx.x;
    int o = t & 63, rg = t >> 6;
    int lane = t & 31, hw = (t >> 5) & 1;
    int blk = blockIdx.x;

#pragma unroll
    for (int k = 0; k < 16; k++) Wsh[t + 256 * k] = W[t + 256 * k];
    float a1 = a[o], a2 = a[64 + o];

#pragma unroll
    for (int iter = 0; iter < 2; iter++) {
        __syncthreads();
        {
            int rr = t >> 4, f4 = t & 15;
            *(float4*)&hsh[rr][f4 * 4] =
                *(const float4*)(h + (size_t)(blk * 32 + iter * 16 + rr) * 64 + f4 * 4);
        }
        __syncthreads();

        float acc[4] = {0.f, 0.f, 0.f, 0.f};
#pragma unroll
        for (int f4 = 0; f4 < 16; f4++) {
            float w0 = Wsh[(f4 * 4 + 0) * 64 + o];
            float w1 = Wsh[(f4 * 4 + 1) * 64 + o];
            float w2 = Wsh[(f4 * 4 + 2) * 64 + o];
            float w3 = Wsh[(f4 * 4 + 3) * 64 + o];
#pragma unroll
            for (int r = 0; r < 4; r++) {
                float4 hv = *(const float4*)&hsh[rg * 4 + r][f4 * 4];
                acc[r] += hv.x * w0 + hv.y * w1 + hv.z * w2 + hv.w * w3;
            }
        }
        int jloc = iter * 16 + rg * 4;
        *(half2*)&Tsh[o][jloc]     = __floats2half2_rn(acc[0], acc[1]);
        *(half2*)&Tsh[o][jloc + 2] = __floats2half2_rn(acc[2], acc[3]);

#pragma unroll
        for (int r = 0; r < 4; r++) {
            float sv = acc[r] * a1;
            float tv = acc[r] * a2;
#pragma unroll
            for (int off = 16; off; off >>= 1) {
                sv += __shfl_down_sync(0xffffffffu, sv, off);
                tv += __shfl_down_sync(0xffffffffu, tv, off);
            }
            if (lane == 0) { red[rg * 4 + r][hw][0] = sv; red[rg * 4 + r][hw][1] = tv; }
        }
        __syncthreads();
        if (t < 16) {
            int row = blk * 32 + iter * 16 + t;
            g_s[row] = red[t][0][0] + red[t][1][0];
            g_t[row] = red[t][0][1] + red[t][1][1];
        }
    }
    __syncthreads();
    {
        int f = t >> 2, c = t & 3;
        uint4 v = *(const uint4*)&Tsh[f][c * 8];
        int b  = (blk * 32) >> 11;
        int j0 = (blk * 32) & 2047;
        *(uint4*)(g_WhT + (size_t)(b * 64 + f) * Nn + j0 + c * 8) = v;
    }
}

// ---------------------------------------------------------------------------
// Kernel B: per-batch tmax
// ---------------------------------------------------------------------------
__global__ void __launch_bounds__(256) kB() {
    __shared__ float red[256];
    int b = blockIdx.x, t = threadIdx.x;
    float m = -1e30f;
#pragma unroll
    for (int k = 0; k < 8; k++) m = fmaxf(m, g_t[b * Nn + t + 256 * k]);
    red[t] = m;
    __syncthreads();
#pragma unroll
    for (int s = 128; s; s >>= 1) {
        if (t < s) red[t] = fmaxf(red[t], red[t + s]);
        __syncthreads();
    }
    if (t == 0) g_tmax[b] = red[0];
}

// ---------------------------------------------------------------------------
// Kernel D: fused masked softmax + HMMA P@Wh + ELU, single adj pass.
// P computed directly into mma A-fragments (registers) -> no P smem, 1
// barrier/iter. Wh tiles via cp.async, triple-buffered, depth-2 prefetch.
// adj prefetched 2 tiles deep in registers.
// ---------------------------------------------------------------------------
#define PSTR     72                      // wsh row stride in halves (144B)
#define WTILE_B  (64 * PSTR * 2)         // 9216 bytes per Wh buffer
#define OFF_WSH  0                       // 3 buffers: 27648
#define OFF_TB   27648                   // 2048 f32
#define OFF_TBP  35840                   // 2048 f32
#define OFF_SA   44032                   // 128 f32
#define OFF_SAP  44544                   // 128 f32
#define OFF_LIN  45056                   // 128 f32
#define SMEM_TOT 45568

__global__ void __launch_bounds__(256) kD(const int* __restrict__ adj,
                                          float* __restrict__ out) {
    extern __shared__ char sm[];
    __half* wsh = (__half*)(sm + OFF_WSH);
    float*  tB  = (float*)(sm + OFF_TB);
    float*  tBp = (float*)(sm + OFF_TBP);
    float*  sA  = (float*)(sm + OFF_SA);
    float*  sAp = (float*)(sm + OFF_SAP);
    float*  lin = (float*)(sm + OFF_LIN);

    int t = threadIdx.x, w = t >> 5, lane = t & 31;
    int b = blockIdx.y, i0 = blockIdx.x * 128;
    float tmax = g_tmax[b];

    int lr0 = w * 16 + (lane >> 2), lr1 = lr0 + 8;
    int c2 = (lane & 3) * 2;
    const int* arow0 = adj + (size_t)(b * Nn + i0 + lr0) * Nn;
    const int* arow1 = adj + (size_t)(b * Nn + i0 + lr1) * Nn;
    const __half* whb = g_WhT + (size_t)b * 64 * Nn;
    uint32_t wsh_u = su32(wsh);

#define LOAD_ADJ(set, k) do { int _j0 = (k) * 64;                          \
    _Pragma("unroll")                                                       \
    for (int _kc = 0; _kc < 4; _kc++) {                                     \
        int _cb = _j0 + _kc * 16 + c2;                                      \
        (set)[_kc * 4 + 0] = *(const int2*)(arow0 + _cb);                   \
        (set)[_kc * 4 + 1] = *(const int2*)(arow1 + _cb);                   \
        (set)[_kc * 4 + 2] = *(const int2*)(arow0 + _cb + 8);               \
        (set)[_kc * 4 + 3] = *(const int2*)(arow1 + _cb + 8);               \
    } } while (0)

#define ISSUE_WH(k) do {                                                    \
    int _buf = (k) % 3;                                                     \
    int _f = t >> 3, _cc = t & 7;                                           \
    const __half* _s0 = whb + (size_t)_f * Nn + (k) * 64 + _cc * 8;         \
    uint32_t _d0 = wsh_u + _buf * WTILE_B + _f * (PSTR * 2) + _cc * 16;     \
    CP16(_d0, _s0);                                                         \
    CP16(_d0 + 32 * (PSTR * 2), _s0 + (size_t)32 * Nn);                     \
    CP_COMMIT(); } while (0)

    int2 aA[16], aB[16];
    LOAD_ADJ(aA, 0);
    LOAD_ADJ(aB, 1);
    ISSUE_WH(0);
    ISSUE_WH(1);

    // exp tables
#pragma unroll
    for (int q = 0; q < 8; q++) {
        int j = t + 256 * q;
        float dd = g_t[b * Nn + j] - tmax;
        tB[j]  = __expf(dd);
        tBp[j] = __expf(ALPHA * dd);
    }
    if (t < 128) {
        float x = g_s[b * Nn + i0 + t] + tmax;
        float m = fmaxf(x, ALPHA * x);
        sA[t]  = __expf(x - m);
        sAp[t] = __expf(ALPHA * x - m);
    }
    __syncthreads();

    float Ai0 = sA[lr0], Ap0 = sAp[lr0];
    float Ai1 = sA[lr1], Ap1 = sAp[lr1];

    int mi = lane >> 3, r8 = lane & 7;
    uint32_t b_row_off = ((mi >> 1) * 8 + r8) * (PSTR * 2) + (mi & 1) * 16;

    float d[8][4];
#pragma unroll
    for (int nb = 0; nb < 8; nb++)
#pragma unroll
        for (int q = 0; q < 4; q++) d[nb][q] = 0.f;
    float rsum0 = 0.f, rsum1 = 0.f;

    const float2* tB2  = (const float2*)tB;
    const float2* tBp2 = (const float2*)tBp;

#define PROCESS(k, AREG) do {                                               \
    CP_WAIT1();                                                             \
    __syncthreads();                                                        \
    uint32_t _wb = wsh_u + ((k) % 3) * WTILE_B;                             \
    _Pragma("unroll")                                                       \
    for (int kc = 0; kc < 4; kc++) {                                        \
        int cbh = ((k) * 64 + kc * 16 + c2) >> 1;                           \
        float2 B0 = tB2[cbh],  B1 = tB2[cbh + 4];                           \
        float2 C0 = tBp2[cbh], C1 = tBp2[cbh + 4];                          \
        int2 q00 = (AREG)[kc * 4 + 0], q10 = (AREG)[kc * 4 + 1];            \
        int2 q01 = (AREG)[kc * 4 + 2], q11 = (AREG)[kc * 4 + 3];            \
        float p00 = q00.x ? fmaxf(Ai0 * B0.x, Ap0 * C0.x) : 0.f;            \
        float p01 = q00.y ? fmaxf(Ai0 * B0.y, Ap0 * C0.y) : 0.f;            \
        float p02 = q01.x ? fmaxf(Ai0 * B1.x, Ap0 * C1.x) : 0.f;            \
        float p03 = q01.y ? fmaxf(Ai0 * B1.y, Ap0 * C1.y) : 0.f;            \
        float p10 = q10.x ? fmaxf(Ai1 * B0.x, Ap1 * C0.x) : 0.f;            \
        float p11 = q10.y ? fmaxf(Ai1 * B0.y, Ap1 * C0.y) : 0.f;            \
        float p12 = q11.x ? fmaxf(Ai1 * B1.x, Ap1 * C1.x) : 0.f;            \
        float p13 = q11.y ? fmaxf(Ai1 * B1.y, Ap1 * C1.y) : 0.f;            \
        rsum0 += (p00 + p01) + (p02 + p03);                                 \
        rsum1 += (p10 + p11) + (p12 + p13);                                 \
        uint32_t fa0, fa1, fa2, fa3;                                        \
        CVTH2(fa0, p00, p01); CVTH2(fa1, p10, p11);                         \
        CVTH2(fa2, p02, p03); CVTH2(fa3, p12, p13);                         \
        _Pragma("unroll")                                                   \
        for (int nbp = 0; nbp < 4; nbp++) {                                 \
            uint32_t b0, b1, b2, b3;                                        \
            LDSM4(b0, b1, b2, b3,                                           \
                  _wb + nbp * 16 * (PSTR * 2) + b_row_off + kc * 32);       \
            MMA16816(d[nbp * 2],     fa0, fa1, fa2, fa3, b0, b1);           \
            MMA16816(d[nbp * 2 + 1], fa0, fa1, fa2, fa3, b2, b3);           \
        }                                                                   \
    }                                                                       \
    if ((k) < 30) { LOAD_ADJ(AREG, (k) + 2); ISSUE_WH((k) + 2); }           \
    else { CP_COMMIT(); } } while (0)

    for (int k = 0; k < 32; k += 2) {
        PROCESS(k, aA);
        PROCESS(k + 1, aB);
    }

    // row sums: quad reduce -> lin
    rsum0 += __shfl_xor_sync(0xffffffffu, rsum0, 1);
    rsum0 += __shfl_xor_sync(0xffffffffu, rsum0, 2);
    rsum1 += __shfl_xor_sync(0xffffffffu, rsum1, 1);
    rsum1 += __shfl_xor_sync(0xffffffffu, rsum1, 2);
    if ((lane & 3) == 0) {
        lin[lr0] = 1.0f / rsum0;
        lin[lr1] = 1.0f / rsum1;
    }
    __syncthreads();

    float l0 = lin[lr0], l1 = lin[lr1];
    float* o0 = out + (size_t)(b * Nn + i0 + lr0) * 64 + c2;
    float* o1 = out + (size_t)(b * Nn + i0 + lr1) * 64 + c2;
#pragma unroll
    for (int nb = 0; nb < 8; nb++) {
        float x0 = d[nb][0] * l0, x1 = d[nb][1] * l0;
        float y0 = d[nb][2] * l1, y1 = d[nb][3] * l1;
        float2 v0, v1;
        v0.x = x0 > 0.f ? x0 : expm1f(x0);
        v0.y = x1 > 0.f ? x1 : expm1f(x1);
        v1.x = y0 > 0.f ? y0 : expm1f(y0);
        v1.y = y1 > 0.f ? y1 : expm1f(y1);
        *(float2*)(o0 + nb * 8) = v0;
        *(float2*)(o1 + nb * 8) = v1;
    }
}

// ---------------------------------------------------------------------------
extern "C" void kernel_launch(void* const* d_in, const int* in_sizes, int n_in,
                              void* d_out, int out_size) {
    const float* h   = (const float*)d_in[0];   // (8,2048,64) f32
    const int*   adj = (const int*)d_in[1];     // (8,2048,2048) i32
    const float* W   = (const float*)d_in[2];   // (64,64) f32
    const float* a   = (const float*)d_in[3];   // (128,1) f32
    float* out = (float*)d_out;                 // (8,2048,64) f32

    kA<<<(Bb * Nn) / 32, 256>>>(h, W, a);
    kB<<<Bb, 256>>>();
    kD<<<dim3(Nn / 128, Bb), 256, SMEM_TOT>>>(adj, out);
}

// round 8
// speedup vs baseline: 1.8560x; 1.8560x over previous
#include <cuda_runtime.h>
#include <cuda_fp16.h>
#include <cstdint>

#define Bb 8
#define Nn 2048
#define ALPHA 0.2f

// ---------------- device globals (no allocation allowed) -------------------
__device__ float    g_s[Bb * Nn];
__device__ float    g_t[Bb * Nn];
__device__ float    g_tmax[Bb];
__device__ __half   g_WhT[Bb * 64 * Nn];       // [b][f][j], fp16, 2MB
__device__ uint32_t g_adjbits[Bb * Nn * 64];   // adj bit-packed, 4MB

// ---------------- PTX helpers ----------------------------------------------
__device__ __forceinline__ uint32_t su32(const void* p) {
    uint32_t a;
    asm("{ .reg .u64 t; cvta.to.shared.u64 t, %1; cvt.u32.u64 %0, t; }"
        : "=r"(a) : "l"(p));
    return a;
}
#define CVTH2(r, lo, hi) \
    asm("cvt.rn.f16x2.f32 %0, %2, %1;" : "=r"(r) : "f"(lo), "f"(hi))

#define LDSM4(r0, r1, r2, r3, addr) \
    asm volatile("ldmatrix.sync.aligned.m8n8.x4.shared.b16 {%0,%1,%2,%3}, [%4];" \
                 : "=r"(r0), "=r"(r1), "=r"(r2), "=r"(r3) : "r"(addr))

#define MMA16816(dd, a0, a1, a2, a3, b0, b1) \
    asm volatile("mma.sync.aligned.m16n8k16.row.col.f32.f16.f16.f32 " \
                 "{%0,%1,%2,%3}, {%4,%5,%6,%7}, {%8,%9}, {%0,%1,%2,%3};" \
                 : "+f"((dd)[0]), "+f"((dd)[1]), "+f"((dd)[2]), "+f"((dd)[3]) \
                 : "r"(a0), "r"(a1), "r"(a2), "r"(a3), "r"(b0), "r"(b1))

#define CP16(dst, src) \
    asm volatile("cp.async.cg.shared.global [%0], [%1], 16;" \
                 :: "r"(dst), "l"(src) : "memory")
#define CP_COMMIT() asm volatile("cp.async.commit_group;" ::: "memory")
#define CP_WAIT1()  asm volatile("cp.async.wait_group 1;" ::: "memory")

// ---------------------------------------------------------------------------
// Kernel A: Wh = h @ W (f32 regs); emits s, t (f32) and WhT (fp16, [b][f][j]).
// ---------------------------------------------------------------------------
__global__ void __launch_bounds__(256) kA(const float* __restrict__ h,
                                          const float* __restrict__ W,
                                          const float* __restrict__ a) {
    __shared__ float  Wsh[64 * 64];
    __shared__ float  hsh[16][64];
    __shared__ float  red[16][2][2];
    __shared__ __half Tsh[64][40];

    int t = threadIdx.x;
    int o = t & 63, rg = t >> 6;
    int lane = t & 31, hw = (t >> 5) & 1;
    int blk = blockIdx.x;

#pragma unroll
    for (int k = 0; k < 16; k++) Wsh[t + 256 * k] = W[t + 256 * k];
    float a1 = a[o], a2 = a[64 + o];

#pragma unroll
    for (int iter = 0; iter < 2; iter++) {
        __syncthreads();
        {
            int rr = t >> 4, f4 = t & 15;
            *(float4*)&hsh[rr][f4 * 4] =
                *(const float4*)(h + (size_t)(blk * 32 + iter * 16 + rr) * 64 + f4 * 4);
        }
        __syncthreads();

        float acc[4] = {0.f, 0.f, 0.f, 0.f};
#pragma unroll
        for (int f4 = 0; f4 < 16; f4++) {
            float w0 = Wsh[(f4 * 4 + 0) * 64 + o];
            float w1 = Wsh[(f4 * 4 + 1) * 64 + o];
            float w2 = Wsh[(f4 * 4 + 2) * 64 + o];
            float w3 = Wsh[(f4 * 4 + 3) * 64 + o];
#pragma unroll
            for (int r = 0; r < 4; r++) {
                float4 hv = *(const float4*)&hsh[rg * 4 + r][f4 * 4];
                acc[r] += hv.x * w0 + hv.y * w1 + hv.z * w2 + hv.w * w3;
            }
        }
        int jloc = iter * 16 + rg * 4;
        *(half2*)&Tsh[o][jloc]     = __floats2half2_rn(acc[0], acc[1]);
        *(half2*)&Tsh[o][jloc + 2] = __floats2half2_rn(acc[2], acc[3]);

#pragma unroll
        for (int r = 0; r < 4; r++) {
            float sv = acc[r] * a1;
            float tv = acc[r] * a2;
#pragma unroll
            for (int off = 16; off; off >>= 1) {
                sv += __shfl_down_sync(0xffffffffu, sv, off);
                tv += __shfl_down_sync(0xffffffffu, tv, off);
            }
            if (lane == 0) { red[rg * 4 + r][hw][0] = sv; red[rg * 4 + r][hw][1] = tv; }
        }
        __syncthreads();
        if (t < 16) {
            int row = blk * 32 + iter * 16 + t;
            g_s[row] = red[t][0][0] + red[t][1][0];
            g_t[row] = red[t][0][1] + red[t][1][1];
        }
    }
    __syncthreads();
    {
        int f = t >> 2, c = t & 3;
        uint4 v = *(const uint4*)&Tsh[f][c * 8];
        int b  = (blk * 32) >> 11;
        int j0 = (blk * 32) & 2047;
        *(uint4*)(g_WhT + (size_t)(b * 64 + f) * Nn + j0 + c * 8) = v;
    }
}

// ---------------------------------------------------------------------------
// Kernel B: per-batch tmax
// ---------------------------------------------------------------------------
__global__ void __launch_bounds__(256) kB() {
    __shared__ float red[256];
    int b = blockIdx.x, t = threadIdx.x;
    float m = -1e30f;
#pragma unroll
    for (int k = 0; k < 8; k++) m = fmaxf(m, g_t[b * Nn + t + 256 * k]);
    red[t] = m;
    __syncthreads();
#pragma unroll
    for (int s = 128; s; s >>= 1) {
        if (t < s) red[t] = fmaxf(red[t], red[t + s]);
        __syncthreads();
    }
    if (t == 0) g_tmax[b] = red[0];
}

// ---------------------------------------------------------------------------
// Kernel P: bit-pack adj (134MB int32 -> 4MB bits). Pure streaming; warp
// ballots. Each warp-iter: 128 ints -> 4 words -> one uint4 store (lane 0).
// ---------------------------------------------------------------------------
__global__ void __launch_bounds__(256) kP(const int* __restrict__ adj) {
    int nw = gridDim.x * 8;
    int gw = blockIdx.x * 8 + (threadIdx.x >> 5);
    int lane = threadIdx.x & 31;
    const size_t total = (size_t)Bb * Nn * Nn;
    for (size_t base = (size_t)gw * 128; base < total; base += (size_t)nw * 128) {
        int v0 = adj[base + lane];
        int v1 = adj[base + 32 + lane];
        int v2 = adj[base + 64 + lane];
        int v3 = adj[base + 96 + lane];
        uint32_t b0 = __ballot_sync(0xffffffffu, v0 > 0);
        uint32_t b1 = __ballot_sync(0xffffffffu, v1 > 0);
        uint32_t b2 = __ballot_sync(0xffffffffu, v2 > 0);
        uint32_t b3 = __ballot_sync(0xffffffffu, v3 > 0);
        if (lane == 0)
            *(uint4*)(g_adjbits + base / 32) = make_uint4(b0, b1, b2, b3);
    }
}

// ---------------------------------------------------------------------------
// Kernel D: fused masked softmax + HMMA P@Wh + ELU, reading bit-packed adj.
// P computed directly into mma A-fragments (registers): no P smem, one
// barrier/iter. Wh tiles via cp.async, triple-buffered, depth-2 prefetch.
// p = bit ? max(A_i*B_j, A'_i*B'_j) : 0  (exact exp factorization).
// ---------------------------------------------------------------------------
#define PSTR     72                      // wsh row stride in halves (144B)
#define WTILE_B  (64 * PSTR * 2)         // 9216 bytes per Wh buffer
#define OFF_WSH  0                       // 3 buffers: 27648
#define OFF_TB   27648                   // 2048 f32
#define OFF_TBP  35840                   // 2048 f32
#define OFF_SA   44032                   // 128 f32
#define OFF_SAP  44544                   // 128 f32
#define OFF_LIN  45056                   // 128 f32
#define SMEM_TOT 45568

__global__ void __launch_bounds__(256) kD(float* __restrict__ out) {
    extern __shared__ char sm[];
    __half* wsh = (__half*)(sm + OFF_WSH);
    float*  tB  = (float*)(sm + OFF_TB);
    float*  tBp = (float*)(sm + OFF_TBP);
    float*  sA  = (float*)(sm + OFF_SA);
    float*  sAp = (float*)(sm + OFF_SAP);
    float*  lin = (float*)(sm + OFF_LIN);

    int t = threadIdx.x, w = t >> 5, lane = t & 31;
    int b = blockIdx.y, i0 = blockIdx.x * 128;
    float tmax = g_tmax[b];

    int lr0 = w * 16 + (lane >> 2), lr1 = lr0 + 8;
    int c2 = (lane & 3) * 2;
    const uint32_t* bits0 = g_adjbits + (size_t)(b * Nn + i0 + lr0) * 64;
    const uint32_t* bits1 = g_adjbits + (size_t)(b * Nn + i0 + lr1) * 64;
    const __half* whb = g_WhT + (size_t)b * 64 * Nn;
    uint32_t wsh_u = su32(wsh);

#define ISSUE_WH(k) do {                                                    \
    int _buf = (k) % 3;                                                     \
    int _f = t >> 3, _cc = t & 7;                                           \
    const __half* _s0 = whb + (size_t)_f * Nn + (k) * 64 + _cc * 8;         \
    uint32_t _d0 = wsh_u + _buf * WTILE_B + _f * (PSTR * 2) + _cc * 16;     \
    CP16(_d0, _s0);                                                         \
    CP16(_d0 + 32 * (PSTR * 2), _s0 + (size_t)32 * Nn);                     \
    CP_COMMIT(); } while (0)

    ISSUE_WH(0);
    ISSUE_WH(1);

    // exp tables
#pragma unroll
    for (int q = 0; q < 8; q++) {
        int j = t + 256 * q;
        float dd = g_t[b * Nn + j] - tmax;
        tB[j]  = __expf(dd);
        tBp[j] = __expf(ALPHA * dd);
    }
    if (t < 128) {
        float x = g_s[b * Nn + i0 + t] + tmax;
        float m = fmaxf(x, ALPHA * x);
        sA[t]  = __expf(x - m);
        sAp[t] = __expf(ALPHA * x - m);
    }
    __syncthreads();

    float Ai0 = sA[lr0], Ap0 = sAp[lr0];
    float Ai1 = sA[lr1], Ap1 = sAp[lr1];

    int mi = lane >> 3, r8 = lane & 7;
    uint32_t b_row_off = ((mi >> 1) * 8 + r8) * (PSTR * 2) + (mi & 1) * 16;

    float d[8][4];
#pragma unroll
    for (int nb = 0; nb < 8; nb++)
#pragma unroll
        for (int q = 0; q < 4; q++) d[nb][q] = 0.f;
    float rsum0 = 0.f, rsum1 = 0.f;

    const float2* tB2  = (const float2*)tB;
    const float2* tBp2 = (const float2*)tBp;

    uint2 awc0 = *(const uint2*)bits0;    // current tile bit words
    uint2 awc1 = *(const uint2*)bits1;
    uint2 awn0, awn1;                     // next tile

    for (int k = 0; k < 32; k++) {
        CP_WAIT1();
        __syncthreads();
        if (k < 31) {
            awn0 = *(const uint2*)(bits0 + (k + 1) * 2);
            awn1 = *(const uint2*)(bits1 + (k + 1) * 2);
        }
        uint32_t wb = wsh_u + (k % 3) * WTILE_B;
#pragma unroll
        for (int kc = 0; kc < 4; kc++) {
            uint32_t wA = (kc & 2) ? awc0.y : awc0.x;
            uint32_t wB = (kc & 2) ? awc1.y : awc1.x;
            int sh = ((kc & 1) << 4) + c2;
            int cbh = (k * 64 + kc * 16 + c2) >> 1;
            float2 B0 = tB2[cbh],  B1 = tB2[cbh + 4];
            float2 C0 = tBp2[cbh], C1 = tBp2[cbh + 4];

            float p00 = ((wA >> sh) & 1u)       ? fmaxf(Ai0 * B0.x, Ap0 * C0.x) : 0.f;
            float p01 = ((wA >> (sh + 1)) & 1u) ? fmaxf(Ai0 * B0.y, Ap0 * C0.y) : 0.f;
            float p02 = ((wA >> (sh + 8)) & 1u) ? fmaxf(Ai0 * B1.x, Ap0 * C1.x) : 0.f;
            float p03 = ((wA >> (sh + 9)) & 1u) ? fmaxf(Ai0 * B1.y, Ap0 * C1.y) : 0.f;
            float p10 = ((wB >> sh) & 1u)       ? fmaxf(Ai1 * B0.x, Ap1 * C0.x) : 0.f;
            float p11 = ((wB >> (sh + 1)) & 1u) ? fmaxf(Ai1 * B0.y, Ap1 * C0.y) : 0.f;
            float p12 = ((wB >> (sh + 8)) & 1u) ? fmaxf(Ai1 * B1.x, Ap1 * C1.x) : 0.f;
            float p13 = ((wB >> (sh + 9)) & 1u) ? fmaxf(Ai1 * B1.y, Ap1 * C1.y) : 0.f;

            rsum0 += (p00 + p01) + (p02 + p03);
            rsum1 += (p10 + p11) + (p12 + p13);

            uint32_t fa0, fa1, fa2, fa3;
            CVTH2(fa0, p00, p01); CVTH2(fa1, p10, p11);
            CVTH2(fa2, p02, p03); CVTH2(fa3, p12, p13);
#pragma unroll
            for (int nbp = 0; nbp < 4; nbp++) {
                uint32_t b0, b1, b2, b3;
                LDSM4(b0, b1, b2, b3,
                      wb + nbp * 16 * (PSTR * 2) + b_row_off + kc * 32);
                MMA16816(d[nbp * 2],     fa0, fa1, fa2, fa3, b0, b1);
                MMA16816(d[nbp * 2 + 1], fa0, fa1, fa2, fa3, b2, b3);
            }
        }
        awc0 = awn0; awc1 = awn1;
        if (k < 30) ISSUE_WH(k + 2);
        else CP_COMMIT();
    }

    // row sums: quad reduce -> lin
    rsum0 += __shfl_xor_sync(0xffffffffu, rsum0, 1);
    rsum0 += __shfl_xor_sync(0xffffffffu, rsum0, 2);
    rsum1 += __shfl_xor_sync(0xffffffffu, rsum1, 1);
    rsum1 += __shfl_xor_sync(0xffffffffu, rsum1, 2);
    if ((lane & 3) == 0) {
        lin[lr0] = 1.0f / rsum0;
        lin[lr1] = 1.0f / rsum1;
    }
    __syncthreads();

    float l0 = lin[lr0], l1 = lin[lr1];
    float* o0 = out + (size_t)(b * Nn + i0 + lr0) * 64 + c2;
    float* o1 = out + (size_t)(b * Nn + i0 + lr1) * 64 + c2;
#pragma unroll
    for (int nb = 0; nb < 8; nb++) {
        float x0 = d[nb][0] * l0, x1 = d[nb][1] * l0;
        float y0 = d[nb][2] * l1, y1 = d[nb][3] * l1;
        float2 v0, v1;
        v0.x = x0 > 0.f ? x0 : expm1f(x0);
        v0.y = x1 > 0.f ? x1 : expm1f(x1);
        v1.x = y0 > 0.f ? y0 : expm1f(y0);
        v1.y = y1 > 0.f ? y1 : expm1f(y1);
        *(float2*)(o0 + nb * 8) = v0;
        *(float2*)(o1 + nb * 8) = v1;
    }
}

// ---------------------------------------------------------------------------
extern "C" void kernel_launch(void* const* d_in, const int* in_sizes, int n_in,
                              void* d_out, int out_size) {
    const float* h   = (const float*)d_in[0];   // (8,2048,64) f32
    const int*   adj = (const int*)d_in[1];     // (8,2048,2048) i32
    const float* W   = (const float*)d_in[2];   // (64,64) f32
    const float* a   = (const float*)d_in[3];   // (128,1) f32
    float* out = (float*)d_out;                 // (8,2048,64) f32

    kP<<<2048, 256>>>(adj);
    kA<<<(Bb * Nn) / 32, 256>>>(h, W, a);
    kB<<<Bb, 256>>>();
    kD<<<dim3(Nn / 128, Bb), 256, SMEM_TOT>>>(out);
}